// round 1
// baseline (speedup 1.0000x reference)
#include <cuda_runtime.h>
#include <cstdint>

#define B_  512
#define T_  100
#define L_  256
#define D_  128
#define P_  9
#define S_  (B_*T_)        // 51200 sequences
#define NT_ 51100          // total tree nodes
#define G_  512            // 4*D gates

// ---------------- device scratch (static globals: no allocation) ----------------
__device__ float g_wihT[D_*G_];          // w_ih transposed: [k][gate]
__device__ float g_whhT[D_*G_];          // w_hh transposed: [k][gate]
__device__ float g_bias[G_];             // b_ih + b_hh
__device__ int   g_nodes[S_*P_];         // per-sequence path node ids
__device__ int   g_leaf[S_];             // leaf idx or -1 (inactive)
__device__ float g_Gx[(size_t)NT_*G_];   // precomputed node_emb @ w_ih^T + bias (~104MB)

// ---------------- fast activations (fp32, MUFU-based, ~1e-6 rel err) ------------
__device__ __forceinline__ float sigf(float x) {
    return __fdividef(1.0f, 1.0f + __expf(-x));
}
__device__ __forceinline__ float tanhf_fast(float x) {
    return __fdividef(2.0f, 1.0f + __expf(-2.0f * x)) - 1.0f;
}

// ---------------- K0: transpose weights + fuse bias -----------------------------
__global__ void prep_kernel(const float* __restrict__ w_ih, const float* __restrict__ w_hh,
                            const float* __restrict__ b_ih, const float* __restrict__ b_hh) {
    int idx = blockIdx.x * 256 + threadIdx.x;
    if (idx < D_ * G_) {
        int g = idx / D_;
        int k = idx % D_;
        g_wihT[k * G_ + g] = w_ih[idx];
        g_whhT[k * G_ + g] = w_hh[idx];
    }
    if (idx < G_) g_bias[idx] = b_ih[idx] + b_hh[idx];
}

// ---------------- K1: argmax over one-hot rows + gather path node ids -----------
// one warp per (b,t) row of 256 floats
__global__ void leaf_kernel(const float* __restrict__ cross, const int* __restrict__ paths) {
    int s = blockIdx.x * 8 + threadIdx.y;   // 51200 rows, 8 warps/block, exact
    int lane = threadIdx.x;
    const float4* r4 = (const float4*)(cross + (size_t)s * L_);
    float best = -1e30f;
    int   bidx = 0x7fffffff;
#pragma unroll
    for (int j = 0; j < 2; j++) {
        float4 v = r4[lane * 2 + j];
        int base = lane * 8 + 4 * j;
        if (v.x > best) { best = v.x; bidx = base + 0; }
        if (v.y > best) { best = v.y; bidx = base + 1; }
        if (v.z > best) { best = v.z; bidx = base + 2; }
        if (v.w > best) { best = v.w; bidx = base + 3; }
    }
#pragma unroll
    for (int off = 16; off; off >>= 1) {
        float ob = __shfl_down_sync(0xffffffffu, best, off);
        int   oi = __shfl_down_sync(0xffffffffu, bidx, off);
        if (ob > best || (ob == best && oi < bidx)) { best = ob; bidx = oi; }
    }
    if (lane == 0) {
        bool act = best > 0.0f;     // reference: active = any(cf > 0)
        g_leaf[s] = act ? bidx : -1;
        int t  = s % T_;
        int lf = act ? bidx : 0;    // dummy valid path when inactive (output masked)
        const int* pp = paths + ((size_t)t * L_ + lf) * P_;
#pragma unroll
        for (int p = 0; p < P_; p++) g_nodes[s * P_ + p] = pp[p];
    }
}

// ---------------- K2: Gx = node_emb @ w_ih^T + bias  (51100 x 512, K=128) -------
// block: 32 nodes x 512 gates, 256 threads, thread tile 4x16
__global__ void __launch_bounds__(256, 2) gx_kernel(const float* __restrict__ node_emb) {
    __shared__ float xs[D_ * 32];    // [k][node] 16KB
    __shared__ float ws[16 * G_];    // [k][gate] 32KB chunk
    int tid = threadIdx.x;
    int n0  = blockIdx.x * 32;
    int ug  = tid >> 3;              // unit-group 0..31 (gates 4*ug..)
    int sg  = tid & 7;               // node-group 0..7 (nodes 4*sg..)

    // load 32 node rows transposed into xs
    {
        int row = tid >> 3;
        int kq  = tid & 7;
        int nrow = n0 + row;
#pragma unroll
        for (int j = 0; j < 4; j++) {
            int c4 = kq + 8 * j;
            float4 v = make_float4(0.f, 0.f, 0.f, 0.f);
            if (nrow < NT_) v = ((const float4*)node_emb)[(size_t)nrow * 32 + c4];
            xs[(4 * c4 + 0) * 32 + row] = v.x;
            xs[(4 * c4 + 1) * 32 + row] = v.y;
            xs[(4 * c4 + 2) * 32 + row] = v.z;
            xs[(4 * c4 + 3) * 32 + row] = v.w;
        }
    }

    float acc[4][16];
    {
        float4 bb[4];
#pragma unroll
        for (int ty = 0; ty < 4; ty++) bb[ty] = *(const float4*)&g_bias[4 * ug + 128 * ty];
#pragma unroll
        for (int ss = 0; ss < 4; ss++)
#pragma unroll
            for (int ty = 0; ty < 4; ty++) {
                acc[ss][ty * 4 + 0] = bb[ty].x;
                acc[ss][ty * 4 + 1] = bb[ty].y;
                acc[ss][ty * 4 + 2] = bb[ty].z;
                acc[ss][ty * 4 + 3] = bb[ty].w;
            }
    }

    for (int kc = 0; kc < 8; kc++) {
#pragma unroll
        for (int j = 0; j < 8; j++)
            ((float4*)ws)[j * 256 + tid] = ((const float4*)g_wihT)[kc * 2048 + j * 256 + tid];
        __syncthreads();
#pragma unroll
        for (int k = 0; k < 16; k++) {
            const float4 a  = *(const float4*)&xs[(kc * 16 + k) * 32 + 4 * sg];
            const float4 b0 = *(const float4*)&ws[k * G_ + 4 * ug];
            const float4 b1 = *(const float4*)&ws[k * G_ + 4 * ug + 128];
            const float4 b2 = *(const float4*)&ws[k * G_ + 4 * ug + 256];
            const float4 b3 = *(const float4*)&ws[k * G_ + 4 * ug + 384];
            float av[4] = {a.x, a.y, a.z, a.w};
            float bv[16] = {b0.x, b0.y, b0.z, b0.w, b1.x, b1.y, b1.z, b1.w,
                            b2.x, b2.y, b2.z, b2.w, b3.x, b3.y, b3.z, b3.w};
#pragma unroll
            for (int ss = 0; ss < 4; ss++)
#pragma unroll
                for (int j = 0; j < 16; j++) acc[ss][j] = fmaf(av[ss], bv[j], acc[ss][j]);
        }
        __syncthreads();
    }

#pragma unroll
    for (int ss = 0; ss < 4; ss++) {
        int n = n0 + 4 * sg + ss;
        if (n < NT_) {
#pragma unroll
            for (int ty = 0; ty < 4; ty++) {
                float4 v = make_float4(acc[ss][ty * 4 + 0], acc[ss][ty * 4 + 1],
                                       acc[ss][ty * 4 + 2], acc[ss][ty * 4 + 3]);
                *(float4*)&g_Gx[(size_t)n * G_ + 4 * ug + 128 * ty] = v;
            }
        }
    }
}

// ---------------- K3: 9-step LSTM recurrence ------------------------------------
// block: 32 sequences, 256 threads. h in smem [unit][seq], c in registers.
// thread tile: 4 seqs x 4 units x 4 gate-types -> cell update is thread-local.
__global__ void __launch_bounds__(256, 2) lstm_kernel(float* __restrict__ out) {
    __shared__ float hs[D_ * 32];    // [unit(k)][seq] 16KB
    __shared__ float ws[16 * G_];    // [k][gate] 32KB chunk of w_hh^T
    int tid = threadIdx.x;
    int s0  = blockIdx.x * 32;
    int ug  = tid >> 3;              // 0..31  -> units 4*ug..4*ug+3
    int sg  = tid & 7;               // 0..7   -> seqs 4*sg..4*sg+3

#pragma unroll
    for (int j = 0; j < 16; j++) hs[j * 256 + tid] = 0.0f;
    float creg[16];
#pragma unroll
    for (int j = 0; j < 16; j++) creg[j] = 0.0f;
    float hn[16];
    __syncthreads();

    for (int p = 0; p < P_; p++) {
        float acc[4][16];
        // init accumulators with gathered Gx rows (x @ w_ih^T + bias)
#pragma unroll
        for (int ss = 0; ss < 4; ss++) {
            int nd = g_nodes[(s0 + 4 * sg + ss) * P_ + p];
            const float4* gx = (const float4*)(g_Gx + (size_t)nd * G_);
#pragma unroll
            for (int ty = 0; ty < 4; ty++) {
                float4 v = gx[ug + 32 * ty];
                acc[ss][ty * 4 + 0] = v.x;
                acc[ss][ty * 4 + 1] = v.y;
                acc[ss][ty * 4 + 2] = v.z;
                acc[ss][ty * 4 + 3] = v.w;
            }
        }
        // accumulate h @ w_hh^T
        for (int kc = 0; kc < 8; kc++) {
#pragma unroll
            for (int j = 0; j < 8; j++)
                ((float4*)ws)[j * 256 + tid] = ((const float4*)g_whhT)[kc * 2048 + j * 256 + tid];
            __syncthreads();
#pragma unroll
            for (int k = 0; k < 16; k++) {
                const float4 a  = *(const float4*)&hs[(kc * 16 + k) * 32 + 4 * sg];
                const float4 b0 = *(const float4*)&ws[k * G_ + 4 * ug];
                const float4 b1 = *(const float4*)&ws[k * G_ + 4 * ug + 128];
                const float4 b2 = *(const float4*)&ws[k * G_ + 4 * ug + 256];
                const float4 b3 = *(const float4*)&ws[k * G_ + 4 * ug + 384];
                float av[4] = {a.x, a.y, a.z, a.w};
                float bv[16] = {b0.x, b0.y, b0.z, b0.w, b1.x, b1.y, b1.z, b1.w,
                                b2.x, b2.y, b2.z, b2.w, b3.x, b3.y, b3.z, b3.w};
#pragma unroll
                for (int ss = 0; ss < 4; ss++)
#pragma unroll
                    for (int j = 0; j < 16; j++) acc[ss][j] = fmaf(av[ss], bv[j], acc[ss][j]);
            }
            __syncthreads();
        }
        // cell update: gates i(ty0), f(ty1), g(ty2), o(ty3) for this thread's units
#pragma unroll
        for (int ss = 0; ss < 4; ss++)
#pragma unroll
            for (int uu = 0; uu < 4; uu++) {
                float iv = sigf(acc[ss][0 + uu]);
                float fv = sigf(acc[ss][4 + uu]);
                float gv = tanhf_fast(acc[ss][8 + uu]);
                float ov = sigf(acc[ss][12 + uu]);
                float c  = fmaf(fv, creg[ss * 4 + uu], iv * gv);
                creg[ss * 4 + uu] = c;
                hn[ss * 4 + uu] = ov * tanhf_fast(c);
            }

        if (p < P_ - 1) {
            // all hs reads of this step finished at the last chunk's __syncthreads
#pragma unroll
            for (int ss = 0; ss < 4; ss++)
#pragma unroll
                for (int uu = 0; uu < 4; uu++)
                    hs[(4 * ug + uu) * 32 + 4 * sg + ss] = hn[ss * 4 + uu];
            // next step's first chunk __syncthreads orders these writes before reads
        } else {
#pragma unroll
            for (int ss = 0; ss < 4; ss++) {
                int s = s0 + 4 * sg + ss;
                bool act = g_leaf[s] >= 0;
                float4 v = act ? make_float4(hn[ss * 4 + 0], hn[ss * 4 + 1],
                                             hn[ss * 4 + 2], hn[ss * 4 + 3])
                               : make_float4(0.f, 0.f, 0.f, 0.f);
                *(float4*)&out[(size_t)s * D_ + 4 * ug] = v;
            }
        }
    }
}

// ---------------- launch ---------------------------------------------------------
extern "C" void kernel_launch(void* const* d_in, const int* in_sizes, int n_in,
                              void* d_out, int out_size) {
    const float* cross    = (const float*)d_in[0];
    const float* node_emb = (const float*)d_in[1];
    const float* w_ih     = (const float*)d_in[2];
    const float* w_hh     = (const float*)d_in[3];
    const float* b_ih     = (const float*)d_in[4];
    const float* b_hh     = (const float*)d_in[5];
    const int*   paths    = (const int*)d_in[6];
    float* out = (float*)d_out;

    prep_kernel<<<256, 256>>>(w_ih, w_hh, b_ih, b_hh);
    leaf_kernel<<<S_ / 8, dim3(32, 8)>>>(cross, paths);
    gx_kernel<<<(NT_ + 31) / 32, 256>>>(node_emb);
    lstm_kernel<<<S_ / 32, 256>>>(out);
}

// round 2
// speedup vs baseline: 1.0006x; 1.0006x over previous
#include <cuda_runtime.h>
#include <cstdint>

#define B_  512
#define T_  100
#define L_  256
#define D_  128
#define P_  9
#define S_  (B_*T_)        // 51200 sequences
#define NT_ 51100          // total tree nodes
#define G_  512            // 4*D gates

// ---------------- device scratch (static globals: no allocation) ----------------
__device__ float g_wihT[D_*G_];          // w_ih transposed: [k][gate]
__device__ float g_whhT[D_*G_];          // w_hh transposed: [k][gate]
__device__ float g_bias[G_];             // b_ih + b_hh
__device__ int   g_nodes[S_*P_];         // per-sequence path node ids
__device__ int   g_leaf[S_];             // leaf idx or -1 (inactive)
__device__ float g_Gx[(size_t)NT_*G_];   // precomputed node_emb @ w_ih^T + bias (~104MB)

// ---------------- fast activations (fp32, MUFU-based, ~1e-6 rel err) ------------
__device__ __forceinline__ float sigf(float x) {
    return __fdividef(1.0f, 1.0f + __expf(-x));
}
__device__ __forceinline__ float tanhf_fast(float x) {
    return __fdividef(2.0f, 1.0f + __expf(-2.0f * x)) - 1.0f;
}

// ---------------- K0: transpose weights + fuse bias -----------------------------
__global__ void prep_kernel(const float* __restrict__ w_ih, const float* __restrict__ w_hh,
                            const float* __restrict__ b_ih, const float* __restrict__ b_hh) {
    int idx = blockIdx.x * 256 + threadIdx.x;
    if (idx < D_ * G_) {
        int g = idx / D_;
        int k = idx % D_;
        g_wihT[k * G_ + g] = w_ih[idx];
        g_whhT[k * G_ + g] = w_hh[idx];
    }
    if (idx < G_) g_bias[idx] = b_ih[idx] + b_hh[idx];
}

// ---------------- K1: argmax over one-hot rows + gather path node ids -----------
// one warp per (b,t) row of 256 floats
__global__ void leaf_kernel(const float* __restrict__ cross, const int* __restrict__ paths) {
    int s = blockIdx.x * 8 + threadIdx.y;   // 51200 rows, 8 warps/block, exact
    int lane = threadIdx.x;
    const float4* r4 = (const float4*)(cross + (size_t)s * L_);
    float best = -1e30f;
    int   bidx = 0x7fffffff;
#pragma unroll
    for (int j = 0; j < 2; j++) {
        float4 v = r4[lane * 2 + j];
        int base = lane * 8 + 4 * j;
        if (v.x > best) { best = v.x; bidx = base + 0; }
        if (v.y > best) { best = v.y; bidx = base + 1; }
        if (v.z > best) { best = v.z; bidx = base + 2; }
        if (v.w > best) { best = v.w; bidx = base + 3; }
    }
#pragma unroll
    for (int off = 16; off; off >>= 1) {
        float ob = __shfl_down_sync(0xffffffffu, best, off);
        int   oi = __shfl_down_sync(0xffffffffu, bidx, off);
        if (ob > best || (ob == best && oi < bidx)) { best = ob; bidx = oi; }
    }
    if (lane == 0) {
        bool act = best > 0.0f;     // reference: active = any(cf > 0)
        g_leaf[s] = act ? bidx : -1;
        int t  = s % T_;
        int lf = act ? bidx : 0;    // dummy valid path when inactive (output masked)
        const int* pp = paths + ((size_t)t * L_ + lf) * P_;
#pragma unroll
        for (int p = 0; p < P_; p++) g_nodes[s * P_ + p] = pp[p];
    }
}

// ---------------- K2: Gx = node_emb @ w_ih^T + bias  (51100 x 512, K=128) -------
// block: 32 nodes x 512 gates, 256 threads, thread tile 4x16
__global__ void __launch_bounds__(256, 2) gx_kernel(const float* __restrict__ node_emb) {
    __shared__ float xs[D_ * 32];    // [k][node] 16KB
    __shared__ float ws[16 * G_];    // [k][gate] 32KB chunk
    int tid = threadIdx.x;
    int n0  = blockIdx.x * 32;
    int ug  = tid >> 3;              // unit-group 0..31 (gates 4*ug..)
    int sg  = tid & 7;               // node-group 0..7 (nodes 4*sg..)

    // load 32 node rows transposed into xs
    {
        int row = tid >> 3;
        int kq  = tid & 7;
        int nrow = n0 + row;
#pragma unroll
        for (int j = 0; j < 4; j++) {
            int c4 = kq + 8 * j;
            float4 v = make_float4(0.f, 0.f, 0.f, 0.f);
            if (nrow < NT_) v = ((const float4*)node_emb)[(size_t)nrow * 32 + c4];
            xs[(4 * c4 + 0) * 32 + row] = v.x;
            xs[(4 * c4 + 1) * 32 + row] = v.y;
            xs[(4 * c4 + 2) * 32 + row] = v.z;
            xs[(4 * c4 + 3) * 32 + row] = v.w;
        }
    }

    float acc[4][16];
    {
        float4 bb[4];
#pragma unroll
        for (int ty = 0; ty < 4; ty++) bb[ty] = *(const float4*)&g_bias[4 * ug + 128 * ty];
#pragma unroll
        for (int ss = 0; ss < 4; ss++)
#pragma unroll
            for (int ty = 0; ty < 4; ty++) {
                acc[ss][ty * 4 + 0] = bb[ty].x;
                acc[ss][ty * 4 + 1] = bb[ty].y;
                acc[ss][ty * 4 + 2] = bb[ty].z;
                acc[ss][ty * 4 + 3] = bb[ty].w;
            }
    }

    for (int kc = 0; kc < 8; kc++) {
#pragma unroll
        for (int j = 0; j < 8; j++)
            ((float4*)ws)[j * 256 + tid] = ((const float4*)g_wihT)[kc * 2048 + j * 256 + tid];
        __syncthreads();
#pragma unroll
        for (int k = 0; k < 16; k++) {
            const float4 a  = *(const float4*)&xs[(kc * 16 + k) * 32 + 4 * sg];
            const float4 b0 = *(const float4*)&ws[k * G_ + 4 * ug];
            const float4 b1 = *(const float4*)&ws[k * G_ + 4 * ug + 128];
            const float4 b2 = *(const float4*)&ws[k * G_ + 4 * ug + 256];
            const float4 b3 = *(const float4*)&ws[k * G_ + 4 * ug + 384];
            float av[4] = {a.x, a.y, a.z, a.w};
            float bv[16] = {b0.x, b0.y, b0.z, b0.w, b1.x, b1.y, b1.z, b1.w,
                            b2.x, b2.y, b2.z, b2.w, b3.x, b3.y, b3.z, b3.w};
#pragma unroll
            for (int ss = 0; ss < 4; ss++)
#pragma unroll
                for (int j = 0; j < 16; j++) acc[ss][j] = fmaf(av[ss], bv[j], acc[ss][j]);
        }
        __syncthreads();
    }

#pragma unroll
    for (int ss = 0; ss < 4; ss++) {
        int n = n0 + 4 * sg + ss;
        if (n < NT_) {
#pragma unroll
            for (int ty = 0; ty < 4; ty++) {
                float4 v = make_float4(acc[ss][ty * 4 + 0], acc[ss][ty * 4 + 1],
                                       acc[ss][ty * 4 + 2], acc[ss][ty * 4 + 3]);
                *(float4*)&g_Gx[(size_t)n * G_ + 4 * ug + 128 * ty] = v;
            }
        }
    }
}

// ---------------- K3: 9-step LSTM recurrence ------------------------------------
// block: 32 sequences, 256 threads. h in smem [unit][seq], c in registers.
// thread tile: 4 seqs x 4 units x 4 gate-types -> cell update is thread-local.
__global__ void __launch_bounds__(256, 2) lstm_kernel(float* __restrict__ out) {
    __shared__ float hs[D_ * 32];    // [unit(k)][seq] 16KB
    __shared__ float ws[16 * G_];    // [k][gate] 32KB chunk of w_hh^T
    int tid = threadIdx.x;
    int s0  = blockIdx.x * 32;
    int ug  = tid >> 3;              // 0..31  -> units 4*ug..4*ug+3
    int sg  = tid & 7;               // 0..7   -> seqs 4*sg..4*sg+3

#pragma unroll
    for (int j = 0; j < 16; j++) hs[j * 256 + tid] = 0.0f;
    float creg[16];
#pragma unroll
    for (int j = 0; j < 16; j++) creg[j] = 0.0f;
    float hn[16];
    __syncthreads();

    for (int p = 0; p < P_; p++) {
        float acc[4][16];
        // init accumulators with gathered Gx rows (x @ w_ih^T + bias)
#pragma unroll
        for (int ss = 0; ss < 4; ss++) {
            int nd = g_nodes[(s0 + 4 * sg + ss) * P_ + p];
            const float4* gx = (const float4*)(g_Gx + (size_t)nd * G_);
#pragma unroll
            for (int ty = 0; ty < 4; ty++) {
                float4 v = gx[ug + 32 * ty];
                acc[ss][ty * 4 + 0] = v.x;
                acc[ss][ty * 4 + 1] = v.y;
                acc[ss][ty * 4 + 2] = v.z;
                acc[ss][ty * 4 + 3] = v.w;
            }
        }
        // accumulate h @ w_hh^T
        for (int kc = 0; kc < 8; kc++) {
#pragma unroll
            for (int j = 0; j < 8; j++)
                ((float4*)ws)[j * 256 + tid] = ((const float4*)g_whhT)[kc * 2048 + j * 256 + tid];
            __syncthreads();
#pragma unroll
            for (int k = 0; k < 16; k++) {
                const float4 a  = *(const float4*)&hs[(kc * 16 + k) * 32 + 4 * sg];
                const float4 b0 = *(const float4*)&ws[k * G_ + 4 * ug];
                const float4 b1 = *(const float4*)&ws[k * G_ + 4 * ug + 128];
                const float4 b2 = *(const float4*)&ws[k * G_ + 4 * ug + 256];
                const float4 b3 = *(const float4*)&ws[k * G_ + 4 * ug + 384];
                float av[4] = {a.x, a.y, a.z, a.w};
                float bv[16] = {b0.x, b0.y, b0.z, b0.w, b1.x, b1.y, b1.z, b1.w,
                                b2.x, b2.y, b2.z, b2.w, b3.x, b3.y, b3.z, b3.w};
#pragma unroll
                for (int ss = 0; ss < 4; ss++)
#pragma unroll
                    for (int j = 0; j < 16; j++) acc[ss][j] = fmaf(av[ss], bv[j], acc[ss][j]);
            }
            __syncthreads();
        }
        // cell update: gates i(ty0), f(ty1), g(ty2), o(ty3) for this thread's units
#pragma unroll
        for (int ss = 0; ss < 4; ss++)
#pragma unroll
            for (int uu = 0; uu < 4; uu++) {
                float iv = sigf(acc[ss][0 + uu]);
                float fv = sigf(acc[ss][4 + uu]);
                float gv = tanhf_fast(acc[ss][8 + uu]);
                float ov = sigf(acc[ss][12 + uu]);
                float c  = fmaf(fv, creg[ss * 4 + uu], iv * gv);
                creg[ss * 4 + uu] = c;
                hn[ss * 4 + uu] = ov * tanhf_fast(c);
            }

        if (p < P_ - 1) {
            // all hs reads of this step finished at the last chunk's __syncthreads
#pragma unroll
            for (int ss = 0; ss < 4; ss++)
#pragma unroll
                for (int uu = 0; uu < 4; uu++)
                    hs[(4 * ug + uu) * 32 + 4 * sg + ss] = hn[ss * 4 + uu];
            // next step's first chunk __syncthreads orders these writes before reads
        } else {
#pragma unroll
            for (int ss = 0; ss < 4; ss++) {
                int s = s0 + 4 * sg + ss;
                bool act = g_leaf[s] >= 0;
                float4 v = act ? make_float4(hn[ss * 4 + 0], hn[ss * 4 + 1],
                                             hn[ss * 4 + 2], hn[ss * 4 + 3])
                               : make_float4(0.f, 0.f, 0.f, 0.f);
                *(float4*)&out[(size_t)s * D_ + 4 * ug] = v;
            }
        }
    }
}

// ---------------- launch ---------------------------------------------------------
extern "C" void kernel_launch(void* const* d_in, const int* in_sizes, int n_in,
                              void* d_out, int out_size) {
    const float* cross    = (const float*)d_in[0];
    const float* node_emb = (const float*)d_in[1];
    const float* w_ih     = (const float*)d_in[2];
    const float* w_hh     = (const float*)d_in[3];
    const float* b_ih     = (const float*)d_in[4];
    const float* b_hh     = (const float*)d_in[5];
    const int*   paths    = (const int*)d_in[6];
    float* out = (float*)d_out;

    prep_kernel<<<256, 256>>>(w_ih, w_hh, b_ih, b_hh);
    leaf_kernel<<<S_ / 8, dim3(32, 8)>>>(cross, paths);
    gx_kernel<<<(NT_ + 31) / 32, 256>>>(node_emb);
    lstm_kernel<<<S_ / 32, 256>>>(out);
}

// round 3
// speedup vs baseline: 1.0008x; 1.0001x over previous
#include <cuda_runtime.h>
#include <cstdint>

#define B_  512
#define T_  100
#define L_  256
#define D_  128
#define P_  9
#define S_  (B_*T_)        // 51200 sequences
#define NT_ 51100          // total tree nodes
#define G_  512            // 4*D gates

// ---------------- device scratch (static globals: no allocation) ----------------
__device__ float g_wihT[D_*G_];          // w_ih transposed: [k][gate]
__device__ float g_whhT[D_*G_];          // w_hh transposed: [k][gate]
__device__ float g_bias[G_];             // b_ih + b_hh
__device__ int   g_nodes[S_*P_];         // per-sequence path node ids
__device__ int   g_leaf[S_];             // leaf idx or -1 (inactive)
__device__ float g_Gx[(size_t)NT_*G_];   // precomputed node_emb @ w_ih^T + bias (~104MB)

// ---------------- fast activations (fp32, MUFU-based, ~1e-6 rel err) ------------
__device__ __forceinline__ float sigf(float x) {
    return __fdividef(1.0f, 1.0f + __expf(-x));
}
__device__ __forceinline__ float tanhf_fast(float x) {
    return __fdividef(2.0f, 1.0f + __expf(-2.0f * x)) - 1.0f;
}

// ---------------- K0: transpose weights + fuse bias -----------------------------
__global__ void prep_kernel(const float* __restrict__ w_ih, const float* __restrict__ w_hh,
                            const float* __restrict__ b_ih, const float* __restrict__ b_hh) {
    int idx = blockIdx.x * 256 + threadIdx.x;
    if (idx < D_ * G_) {
        int g = idx / D_;
        int k = idx % D_;
        g_wihT[k * G_ + g] = w_ih[idx];
        g_whhT[k * G_ + g] = w_hh[idx];
    }
    if (idx < G_) g_bias[idx] = b_ih[idx] + b_hh[idx];
}

// ---------------- K1: argmax over one-hot rows + gather path node ids -----------
// one warp per (b,t) row of 256 floats
__global__ void leaf_kernel(const float* __restrict__ cross, const int* __restrict__ paths) {
    int s = blockIdx.x * 8 + threadIdx.y;   // 51200 rows, 8 warps/block, exact
    int lane = threadIdx.x;
    const float4* r4 = (const float4*)(cross + (size_t)s * L_);
    float best = -1e30f;
    int   bidx = 0x7fffffff;
#pragma unroll
    for (int j = 0; j < 2; j++) {
        float4 v = r4[lane * 2 + j];
        int base = lane * 8 + 4 * j;
        if (v.x > best) { best = v.x; bidx = base + 0; }
        if (v.y > best) { best = v.y; bidx = base + 1; }
        if (v.z > best) { best = v.z; bidx = base + 2; }
        if (v.w > best) { best = v.w; bidx = base + 3; }
    }
#pragma unroll
    for (int off = 16; off; off >>= 1) {
        float ob = __shfl_down_sync(0xffffffffu, best, off);
        int   oi = __shfl_down_sync(0xffffffffu, bidx, off);
        if (ob > best || (ob == best && oi < bidx)) { best = ob; bidx = oi; }
    }
    if (lane == 0) {
        bool act = best > 0.0f;     // reference: active = any(cf > 0)
        g_leaf[s] = act ? bidx : -1;
        int t  = s % T_;
        int lf = act ? bidx : 0;    // dummy valid path when inactive (output masked)
        const int* pp = paths + ((size_t)t * L_ + lf) * P_;
#pragma unroll
        for (int p = 0; p < P_; p++) g_nodes[s * P_ + p] = pp[p];
    }
}

// ---------------- K2: Gx = node_emb @ w_ih^T + bias  (51100 x 512, K=128) -------
// block: 32 nodes x 512 gates, 256 threads, thread tile 4x16
__global__ void __launch_bounds__(256, 2) gx_kernel(const float* __restrict__ node_emb) {
    __shared__ float xs[D_ * 32];    // [k][node] 16KB
    __shared__ float ws[16 * G_];    // [k][gate] 32KB chunk
    int tid = threadIdx.x;
    int n0  = blockIdx.x * 32;
    int ug  = tid >> 3;              // unit-group 0..31 (gates 4*ug..)
    int sg  = tid & 7;               // node-group 0..7 (nodes 4*sg..)

    // load 32 node rows transposed into xs
    {
        int row = tid >> 3;
        int kq  = tid & 7;
        int nrow = n0 + row;
#pragma unroll
        for (int j = 0; j < 4; j++) {
            int c4 = kq + 8 * j;
            float4 v = make_float4(0.f, 0.f, 0.f, 0.f);
            if (nrow < NT_) v = ((const float4*)node_emb)[(size_t)nrow * 32 + c4];
            xs[(4 * c4 + 0) * 32 + row] = v.x;
            xs[(4 * c4 + 1) * 32 + row] = v.y;
            xs[(4 * c4 + 2) * 32 + row] = v.z;
            xs[(4 * c4 + 3) * 32 + row] = v.w;
        }
    }

    float acc[4][16];
    {
        float4 bb[4];
#pragma unroll
        for (int ty = 0; ty < 4; ty++) bb[ty] = *(const float4*)&g_bias[4 * ug + 128 * ty];
#pragma unroll
        for (int ss = 0; ss < 4; ss++)
#pragma unroll
            for (int ty = 0; ty < 4; ty++) {
                acc[ss][ty * 4 + 0] = bb[ty].x;
                acc[ss][ty * 4 + 1] = bb[ty].y;
                acc[ss][ty * 4 + 2] = bb[ty].z;
                acc[ss][ty * 4 + 3] = bb[ty].w;
            }
    }

    for (int kc = 0; kc < 8; kc++) {
#pragma unroll
        for (int j = 0; j < 8; j++)
            ((float4*)ws)[j * 256 + tid] = ((const float4*)g_wihT)[kc * 2048 + j * 256 + tid];
        __syncthreads();
#pragma unroll
        for (int k = 0; k < 16; k++) {
            const float4 a  = *(const float4*)&xs[(kc * 16 + k) * 32 + 4 * sg];
            const float4 b0 = *(const float4*)&ws[k * G_ + 4 * ug];
            const float4 b1 = *(const float4*)&ws[k * G_ + 4 * ug + 128];
            const float4 b2 = *(const float4*)&ws[k * G_ + 4 * ug + 256];
            const float4 b3 = *(const float4*)&ws[k * G_ + 4 * ug + 384];
            float av[4] = {a.x, a.y, a.z, a.w};
            float bv[16] = {b0.x, b0.y, b0.z, b0.w, b1.x, b1.y, b1.z, b1.w,
                            b2.x, b2.y, b2.z, b2.w, b3.x, b3.y, b3.z, b3.w};
#pragma unroll
            for (int ss = 0; ss < 4; ss++)
#pragma unroll
                for (int j = 0; j < 16; j++) acc[ss][j] = fmaf(av[ss], bv[j], acc[ss][j]);
        }
        __syncthreads();
    }

#pragma unroll
    for (int ss = 0; ss < 4; ss++) {
        int n = n0 + 4 * sg + ss;
        if (n < NT_) {
#pragma unroll
            for (int ty = 0; ty < 4; ty++) {
                float4 v = make_float4(acc[ss][ty * 4 + 0], acc[ss][ty * 4 + 1],
                                       acc[ss][ty * 4 + 2], acc[ss][ty * 4 + 3]);
                *(float4*)&g_Gx[(size_t)n * G_ + 4 * ug + 128 * ty] = v;
            }
        }
    }
}

// ---------------- K3: 9-step LSTM recurrence ------------------------------------
// block: 32 sequences, 256 threads. h in smem [unit][seq], c in registers.
// thread tile: 4 seqs x 4 units x 4 gate-types -> cell update is thread-local.
__global__ void __launch_bounds__(256, 2) lstm_kernel(float* __restrict__ out) {
    __shared__ float hs[D_ * 32];    // [unit(k)][seq] 16KB
    __shared__ float ws[16 * G_];    // [k][gate] 32KB chunk of w_hh^T
    int tid = threadIdx.x;
    int s0  = blockIdx.x * 32;
    int ug  = tid >> 3;              // 0..31  -> units 4*ug..4*ug+3
    int sg  = tid & 7;               // 0..7   -> seqs 4*sg..4*sg+3

#pragma unroll
    for (int j = 0; j < 16; j++) hs[j * 256 + tid] = 0.0f;
    float creg[16];
#pragma unroll
    for (int j = 0; j < 16; j++) creg[j] = 0.0f;
    float hn[16];
    __syncthreads();

    for (int p = 0; p < P_; p++) {
        float acc[4][16];
        // init accumulators with gathered Gx rows (x @ w_ih^T + bias)
#pragma unroll
        for (int ss = 0; ss < 4; ss++) {
            int nd = g_nodes[(s0 + 4 * sg + ss) * P_ + p];
            const float4* gx = (const float4*)(g_Gx + (size_t)nd * G_);
#pragma unroll
            for (int ty = 0; ty < 4; ty++) {
                float4 v = gx[ug + 32 * ty];
                acc[ss][ty * 4 + 0] = v.x;
                acc[ss][ty * 4 + 1] = v.y;
                acc[ss][ty * 4 + 2] = v.z;
                acc[ss][ty * 4 + 3] = v.w;
            }
        }
        // accumulate h @ w_hh^T
        for (int kc = 0; kc < 8; kc++) {
#pragma unroll
            for (int j = 0; j < 8; j++)
                ((float4*)ws)[j * 256 + tid] = ((const float4*)g_whhT)[kc * 2048 + j * 256 + tid];
            __syncthreads();
#pragma unroll
            for (int k = 0; k < 16; k++) {
                const float4 a  = *(const float4*)&hs[(kc * 16 + k) * 32 + 4 * sg];
                const float4 b0 = *(const float4*)&ws[k * G_ + 4 * ug];
                const float4 b1 = *(const float4*)&ws[k * G_ + 4 * ug + 128];
                const float4 b2 = *(const float4*)&ws[k * G_ + 4 * ug + 256];
                const float4 b3 = *(const float4*)&ws[k * G_ + 4 * ug + 384];
                float av[4] = {a.x, a.y, a.z, a.w};
                float bv[16] = {b0.x, b0.y, b0.z, b0.w, b1.x, b1.y, b1.z, b1.w,
                                b2.x, b2.y, b2.z, b2.w, b3.x, b3.y, b3.z, b3.w};
#pragma unroll
                for (int ss = 0; ss < 4; ss++)
#pragma unroll
                    for (int j = 0; j < 16; j++) acc[ss][j] = fmaf(av[ss], bv[j], acc[ss][j]);
            }
            __syncthreads();
        }
        // cell update: gates i(ty0), f(ty1), g(ty2), o(ty3) for this thread's units
#pragma unroll
        for (int ss = 0; ss < 4; ss++)
#pragma unroll
            for (int uu = 0; uu < 4; uu++) {
                float iv = sigf(acc[ss][0 + uu]);
                float fv = sigf(acc[ss][4 + uu]);
                float gv = tanhf_fast(acc[ss][8 + uu]);
                float ov = sigf(acc[ss][12 + uu]);
                float c  = fmaf(fv, creg[ss * 4 + uu], iv * gv);
                creg[ss * 4 + uu] = c;
                hn[ss * 4 + uu] = ov * tanhf_fast(c);
            }

        if (p < P_ - 1) {
            // all hs reads of this step finished at the last chunk's __syncthreads
#pragma unroll
            for (int ss = 0; ss < 4; ss++)
#pragma unroll
                for (int uu = 0; uu < 4; uu++)
                    hs[(4 * ug + uu) * 32 + 4 * sg + ss] = hn[ss * 4 + uu];
            // next step's first chunk __syncthreads orders these writes before reads
        } else {
#pragma unroll
            for (int ss = 0; ss < 4; ss++) {
                int s = s0 + 4 * sg + ss;
                bool act = g_leaf[s] >= 0;
                float4 v = act ? make_float4(hn[ss * 4 + 0], hn[ss * 4 + 1],
                                             hn[ss * 4 + 2], hn[ss * 4 + 3])
                               : make_float4(0.f, 0.f, 0.f, 0.f);
                *(float4*)&out[(size_t)s * D_ + 4 * ug] = v;
            }
        }
    }
}

// ---------------- launch ---------------------------------------------------------
extern "C" void kernel_launch(void* const* d_in, const int* in_sizes, int n_in,
                              void* d_out, int out_size) {
    const float* cross    = (const float*)d_in[0];
    const float* node_emb = (const float*)d_in[1];
    const float* w_ih     = (const float*)d_in[2];
    const float* w_hh     = (const float*)d_in[3];
    const float* b_ih     = (const float*)d_in[4];
    const float* b_hh     = (const float*)d_in[5];
    const int*   paths    = (const int*)d_in[6];
    float* out = (float*)d_out;

    prep_kernel<<<256, 256>>>(w_ih, w_hh, b_ih, b_hh);
    leaf_kernel<<<S_ / 8, dim3(32, 8)>>>(cross, paths);
    gx_kernel<<<(NT_ + 31) / 32, 256>>>(node_emb);
    lstm_kernel<<<S_ / 32, 256>>>(out);
}

// round 5
// speedup vs baseline: 3.8689x; 3.8660x over previous
#include <cuda_runtime.h>
#include <cuda_bf16.h>
#include <cstdint>

#define B_  512
#define T_  100
#define L_  256
#define D_  128
#define P_  9
#define S_  (B_*T_)        // 51200 (b,t) rows
#define NPT 511            // nodes per tree
#define NT_ (T_*NPT)       // 51100 total tree nodes
#define G_  512            // 4*D gates

// ---------------- device scratch (static globals: no allocation) ----------------
__device__ float g_wihT[D_*G_];          // w_ih transposed: [k][gate]
__device__ float g_whhT[D_*G_];          // w_hh transposed: [k][gate]
__device__ float g_bias[G_];             // b_ih + b_hh
__device__ float g_Gx[(size_t)NT_*G_];   // node_emb @ w_ih^T + bias (~104MB)
__device__ float g_H[(size_t)NT_*D_];    // per-node hidden state (26MB)
__device__ float g_C[(size_t)NT_*D_];    // per-node cell state (26MB)

// ---------------- fast activations (fp32, MUFU-based, ~1e-6 rel err) ------------
__device__ __forceinline__ float sigf(float x) {
    return __fdividef(1.0f, 1.0f + __expf(-x));
}
__device__ __forceinline__ float tanhf_fast(float x) {
    return __fdividef(2.0f, 1.0f + __expf(-2.0f * x)) - 1.0f;
}

// ---------------- K0: transpose weights + fuse bias -----------------------------
__global__ void prep_kernel(const float* __restrict__ w_ih, const float* __restrict__ w_hh,
                            const float* __restrict__ b_ih, const float* __restrict__ b_hh) {
    int idx = blockIdx.x * 256 + threadIdx.x;
    if (idx < D_ * G_) {
        int g = idx / D_;
        int k = idx % D_;
        g_wihT[k * G_ + g] = w_ih[idx];
        g_whhT[k * G_ + g] = w_hh[idx];
    }
    if (idx < G_) g_bias[idx] = b_ih[idx] + b_hh[idx];
}

// ---------------- K1: Gx = node_emb @ w_ih^T + bias  (51100 x 512, K=128) -------
__global__ void __launch_bounds__(256, 2) gx_kernel(const float* __restrict__ node_emb) {
    __shared__ float xs[D_ * 32];    // [k][node]
    __shared__ float ws[16 * G_];    // [k][gate] chunk
    int tid = threadIdx.x;
    int n0  = blockIdx.x * 32;
    int ug  = tid >> 3;
    int sg  = tid & 7;
    {
        int row = tid >> 3;
        int kq  = tid & 7;
        int nrow = n0 + row;
#pragma unroll
        for (int j = 0; j < 4; j++) {
            int c4 = kq + 8 * j;
            float4 v = make_float4(0.f, 0.f, 0.f, 0.f);
            if (nrow < NT_) v = ((const float4*)node_emb)[(size_t)nrow * 32 + c4];
            xs[(4 * c4 + 0) * 32 + row] = v.x;
            xs[(4 * c4 + 1) * 32 + row] = v.y;
            xs[(4 * c4 + 2) * 32 + row] = v.z;
            xs[(4 * c4 + 3) * 32 + row] = v.w;
        }
    }
    float acc[4][16];
    {
        float4 bb[4];
#pragma unroll
        for (int ty = 0; ty < 4; ty++) bb[ty] = *(const float4*)&g_bias[4 * ug + 128 * ty];
#pragma unroll
        for (int ss = 0; ss < 4; ss++)
#pragma unroll
            for (int ty = 0; ty < 4; ty++) {
                acc[ss][ty * 4 + 0] = bb[ty].x;
                acc[ss][ty * 4 + 1] = bb[ty].y;
                acc[ss][ty * 4 + 2] = bb[ty].z;
                acc[ss][ty * 4 + 3] = bb[ty].w;
            }
    }
    for (int kc = 0; kc < 8; kc++) {
#pragma unroll
        for (int j = 0; j < 8; j++)
            ((float4*)ws)[j * 256 + tid] = ((const float4*)g_wihT)[kc * 2048 + j * 256 + tid];
        __syncthreads();
#pragma unroll
        for (int k = 0; k < 16; k++) {
            const float4 a  = *(const float4*)&xs[(kc * 16 + k) * 32 + 4 * sg];
            const float4 b0 = *(const float4*)&ws[k * G_ + 4 * ug];
            const float4 b1 = *(const float4*)&ws[k * G_ + 4 * ug + 128];
            const float4 b2 = *(const float4*)&ws[k * G_ + 4 * ug + 256];
            const float4 b3 = *(const float4*)&ws[k * G_ + 4 * ug + 384];
            float av[4] = {a.x, a.y, a.z, a.w};
            float bv[16] = {b0.x, b0.y, b0.z, b0.w, b1.x, b1.y, b1.z, b1.w,
                            b2.x, b2.y, b2.z, b2.w, b3.x, b3.y, b3.z, b3.w};
#pragma unroll
            for (int ss = 0; ss < 4; ss++)
#pragma unroll
                for (int j = 0; j < 16; j++) acc[ss][j] = fmaf(av[ss], bv[j], acc[ss][j]);
        }
        __syncthreads();
    }
#pragma unroll
    for (int ss = 0; ss < 4; ss++) {
        int n = n0 + 4 * sg + ss;
        if (n < NT_) {
#pragma unroll
            for (int ty = 0; ty < 4; ty++) {
                float4 v = make_float4(acc[ss][ty * 4 + 0], acc[ss][ty * 4 + 1],
                                       acc[ss][ty * 4 + 2], acc[ss][ty * 4 + 3]);
                *(float4*)&g_Gx[(size_t)n * G_ + 4 * ug + 128 * ty] = v;
            }
        }
    }
}

// ---------------- K2: level 0 — root states (h=c=0 => pure activation of Gx) ----
__global__ void level0_kernel() {
    int idx = blockIdx.x * 256 + threadIdx.x;   // 100 trees * 128 units
    if (idx >= T_ * D_) return;
    int t = idx >> 7;
    int u = idx & 127;
    size_t rb = (size_t)(t * NPT) * G_;
    float iv = sigf(g_Gx[rb + u]);
    float gv = tanhf_fast(g_Gx[rb + 256 + u]);
    float ov = sigf(g_Gx[rb + 384 + u]);
    float c  = iv * gv;                          // f*c_prev = 0
    g_C[(size_t)(t * NPT) * D_ + u] = c;
    g_H[(size_t)(t * NPT) * D_ + u] = ov * tanhf_fast(c);
}

// ---------------- K3: tree level step ------------------------------------------
// One GEMM row per PARENT node; result reused for both children (each adds its
// own Gx). Block: 32 parents x 512 gates, 256 threads, thread tile 4x16.
// parent flat index pi -> tree t = pi>>shift, j = pi & (half-1),
// parent local = half-1+j, children local = 2*local+1, 2*local+2.
__global__ void __launch_bounds__(256, 2) level_kernel(int shift, int pcnt) {
    __shared__ float hs[D_ * 32];    // [k][parent]
    __shared__ float ws[16 * G_];    // [k][gate] chunk of w_hh^T
    int tid  = threadIdx.x;
    int p0   = blockIdx.x * 32;
    int half = 1 << shift;
    int ug   = tid >> 3;
    int sg   = tid & 7;

    // load 32 parent h rows transposed into hs
    {
        int row = tid >> 3;
        int kq  = tid & 7;
        int pi  = p0 + row;
        const float4* src = nullptr;
        if (pi < pcnt) {
            int t = pi >> shift;
            int j = pi & (half - 1);
            size_t pgid = (size_t)t * NPT + (half - 1) + j;
            src = (const float4*)(g_H + pgid * D_);
        }
#pragma unroll
        for (int jj = 0; jj < 4; jj++) {
            int c4 = kq + 8 * jj;
            float4 v = src ? src[c4] : make_float4(0.f, 0.f, 0.f, 0.f);
            hs[(4 * c4 + 0) * 32 + row] = v.x;
            hs[(4 * c4 + 1) * 32 + row] = v.y;
            hs[(4 * c4 + 2) * 32 + row] = v.z;
            hs[(4 * c4 + 3) * 32 + row] = v.w;
        }
    }

    float acc[4][16];
#pragma unroll
    for (int ss = 0; ss < 4; ss++)
#pragma unroll
        for (int j = 0; j < 16; j++) acc[ss][j] = 0.0f;

    for (int kc = 0; kc < 8; kc++) {
#pragma unroll
        for (int j = 0; j < 8; j++)
            ((float4*)ws)[j * 256 + tid] = ((const float4*)g_whhT)[kc * 2048 + j * 256 + tid];
        __syncthreads();
#pragma unroll
        for (int k = 0; k < 16; k++) {
            const float4 a  = *(const float4*)&hs[(kc * 16 + k) * 32 + 4 * sg];
            const float4 b0 = *(const float4*)&ws[k * G_ + 4 * ug];
            const float4 b1 = *(const float4*)&ws[k * G_ + 4 * ug + 128];
            const float4 b2 = *(const float4*)&ws[k * G_ + 4 * ug + 256];
            const float4 b3 = *(const float4*)&ws[k * G_ + 4 * ug + 384];
            float av[4] = {a.x, a.y, a.z, a.w};
            float bv[16] = {b0.x, b0.y, b0.z, b0.w, b1.x, b1.y, b1.z, b1.w,
                            b2.x, b2.y, b2.z, b2.w, b3.x, b3.y, b3.z, b3.w};
#pragma unroll
            for (int ss = 0; ss < 4; ss++)
#pragma unroll
                for (int j = 0; j < 16; j++) acc[ss][j] = fmaf(av[ss], bv[j], acc[ss][j]);
        }
        __syncthreads();
    }

    // epilogue: apply both children of each parent
#pragma unroll
    for (int ss = 0; ss < 4; ss++) {
        int pi = p0 + 4 * sg + ss;
        if (pi >= pcnt) continue;
        int t = pi >> shift;
        int j = pi & (half - 1);
        int plocal = (half - 1) + j;
        size_t tb = (size_t)t * NPT;
        float4 cp4 = *(const float4*)(g_C + (tb + plocal) * D_ + 4 * ug);
        float cp[4] = {cp4.x, cp4.y, cp4.z, cp4.w};
#pragma unroll
        for (int ch = 0; ch < 2; ch++) {
            size_t cgid = tb + 2 * plocal + 1 + ch;
            const float* gxr = g_Gx + cgid * G_;
            float4 gi = *(const float4*)(gxr + 4 * ug);
            float4 gf = *(const float4*)(gxr + 128 + 4 * ug);
            float4 gg = *(const float4*)(gxr + 256 + 4 * ug);
            float4 go = *(const float4*)(gxr + 384 + 4 * ug);
            float giv[4] = {gi.x, gi.y, gi.z, gi.w};
            float gfv[4] = {gf.x, gf.y, gf.z, gf.w};
            float ggv[4] = {gg.x, gg.y, gg.z, gg.w};
            float gov[4] = {go.x, go.y, go.z, go.w};
            float hv[4], cv[4];
#pragma unroll
            for (int uu = 0; uu < 4; uu++) {
                float iv = sigf(acc[ss][0 + uu] + giv[uu]);
                float fv = sigf(acc[ss][4 + uu] + gfv[uu]);
                float gv = tanhf_fast(acc[ss][8 + uu] + ggv[uu]);
                float ov = sigf(acc[ss][12 + uu] + gov[uu]);
                float c  = fmaf(fv, cp[uu], iv * gv);
                cv[uu] = c;
                hv[uu] = ov * tanhf_fast(c);
            }
            *(float4*)(g_C + cgid * D_ + 4 * ug) = make_float4(cv[0], cv[1], cv[2], cv[3]);
            *(float4*)(g_H + cgid * D_ + 4 * ug) = make_float4(hv[0], hv[1], hv[2], hv[3]);
        }
    }
}

// ---------------- K4: argmax leaf + gather output -------------------------------
// one warp per (b,t): butterfly-argmax over 256 one-hot floats, then copy the
// leaf node's h row (or zeros if inactive).
__global__ void gather_kernel(const float* __restrict__ cross, float* __restrict__ out) {
    int s = blockIdx.x * 8 + threadIdx.y;
    int lane = threadIdx.x;
    const float4* r4 = (const float4*)(cross + (size_t)s * L_);
    float best = -1e30f;
    int   bidx = 0x7fffffff;
#pragma unroll
    for (int j = 0; j < 2; j++) {
        float4 v = r4[lane * 2 + j];
        int base = lane * 8 + 4 * j;
        if (v.x > best) { best = v.x; bidx = base + 0; }
        if (v.y > best) { best = v.y; bidx = base + 1; }
        if (v.z > best) { best = v.z; bidx = base + 2; }
        if (v.w > best) { best = v.w; bidx = base + 3; }
    }
#pragma unroll
    for (int off = 16; off; off >>= 1) {
        float ob = __shfl_xor_sync(0xffffffffu, best, off);
        int   oi = __shfl_xor_sync(0xffffffffu, bidx, off);
        if (ob > best || (ob == best && oi < bidx)) { best = ob; bidx = oi; }
    }
    bool act = best > 0.0f;                       // reference: any(cf > 0)
    int t = s % T_;
    size_t gid = (size_t)t * NPT + (L_ - 1) + bidx;
    float4 v = act ? ((const float4*)(g_H + gid * D_))[lane]
                   : make_float4(0.f, 0.f, 0.f, 0.f);
    ((float4*)(out + (size_t)s * D_))[lane] = v;
}

// ---------------- launch ---------------------------------------------------------
extern "C" void kernel_launch(void* const* d_in, const int* in_sizes, int n_in,
                              void* d_out, int out_size) {
    const float* cross    = (const float*)d_in[0];
    const float* node_emb = (const float*)d_in[1];
    const float* w_ih     = (const float*)d_in[2];
    const float* w_hh     = (const float*)d_in[3];
    const float* b_ih     = (const float*)d_in[4];
    const float* b_hh     = (const float*)d_in[5];
    float* out = (float*)d_out;

    prep_kernel<<<256, 256>>>(w_ih, w_hh, b_ih, b_hh);
    gx_kernel<<<(NT_ + 31) / 32, 256>>>(node_emb);
    level0_kernel<<<(T_ * D_ + 255) / 256, 256>>>();
    for (int d = 1; d <= 8; d++) {
        int shift = d - 1;
        int pcnt  = T_ << shift;             // parents at this level
        level_kernel<<<(pcnt + 31) / 32, 256>>>(shift, pcnt);
    }
    gather_kernel<<<S_ / 8, dim3(32, 8)>>>(cross, out);
}